// round 10
// baseline (speedup 1.0000x reference)
#include <cuda_runtime.h>

// Integer-exact fused QAT conv stack (bit-exact vs fp32 reference).
// 3-stage smem design, occupancy-max: 24.6KB smem + 32-reg target
// (__launch_bounds__(256,8)) -> 8 blocks/SM.

#define TL 2048      // tile positions per block
#define NT 256       // threads per block

__device__ __forceinline__ int cvtrd(float v) {
    return __float2int_rd(fmaf(v, 128.0f, 0.5f));   // floor(v*128 + 0.5)
}
__device__ __forceinline__ int packsat2(int a, int b, int c) {
    int d;
    asm("cvt.pack.sat.s8.s32.b32 %0, %1, %2, %3;"
        : "=r"(d) : "r"(a), "r"(b), "r"(c));
    return d;
}
// bytes perm of [v0..v3]; same helper for weights and data -> dp4a invariant
__device__ __forceinline__ int pack4sat(int v0, int v1, int v2, int v3) {
    return packsat2(v1, v0, packsat2(v3, v2, 0));
}
__device__ __forceinline__ int qpack(float a, float b, float c, float d) {
    return pack4sat(cvtrd(a), cvtrd(b), cvtrd(c), cvtrd(d));
}

// Stages 2+3, templated on EDGE so interior blocks get a branch-free body.
// wsh layout: [0..23] w1p (oc*3+k), [24..31] bo1, [32..43] w2p (oc*6+k*2+h),
//             [44..45] bo2
template <bool EDGE>
__device__ __forceinline__ void stages23(
    const int* __restrict__ xs, int* __restrict__ ysL, int* __restrict__ ysH,
    const int* __restrict__ wsh, int tid, int ts, int L, float* __restrict__ ob)
{
    // ---- stage 2: y = satpack((conv1 + 128*b + 64) >> 7), 4 pos/thread ----
    for (int g = tid; g < (TL + 4) / 4; g += NT) {
        int m = 4 * g;
        int4 va = *(const int4*)(xs + m);
        int4 vb = *(const int4*)(xs + m + 4);
        int xv[8] = {va.x, va.y, va.z, va.w, vb.x, vb.y, vb.z, vb.w};
        int lo[4], hi[4];
#pragma unroll
        for (int p = 0; p < 4; p++) {
            int x0 = xv[p + 1], x1 = xv[p + 2], x2 = xv[p + 3];
            int yv[8];
#pragma unroll
            for (int oc = 0; oc < 8; oc++) {
                int acc = __dp4a(x0, wsh[oc * 3 + 0], wsh[24 + oc]);
                acc     = __dp4a(x1, wsh[oc * 3 + 1], acc);
                acc     = __dp4a(x2, wsh[oc * 3 + 2], acc);
                yv[oc]  = acc >> 7;
            }
            lo[p] = pack4sat(yv[0], yv[1], yv[2], yv[3]);
            hi[p] = pack4sat(yv[4], yv[5], yv[6], yv[7]);
            if (EDGE) {
                int q = ts - 2 + m + p;
                bool valid = (q >= 0) && (q < L);
                lo[p] = valid ? lo[p] : 0;
                hi[p] = valid ? hi[p] : 0;
            }
        }
        *(int4*)(ysL + m) = make_int4(lo[0], lo[1], lo[2], lo[3]);
        *(int4*)(ysH + m) = make_int4(hi[0], hi[1], hi[2], hi[3]);
    }
    __syncthreads();

    // ---- stage 3: z = dequant(clamp((conv2 + 128*b + 64) >> 7)), 4 pos ----
    for (int g = tid; g < TL / 4; g += NT) {
        int j = 4 * g;
        int4 la = *(const int4*)(ysL + j);
        int4 lb = *(const int4*)(ysL + j + 4);
        int4 ha = *(const int4*)(ysH + j);
        int4 hb = *(const int4*)(ysH + j + 4);
        int YL[8] = {la.x, la.y, la.z, la.w, lb.x, lb.y, lb.z, lb.w};
        int YH[8] = {ha.x, ha.y, ha.z, ha.w, hb.x, hb.y, hb.z, hb.w};
        float f0[4], f1[4];
#pragma unroll
        for (int p = 0; p < 4; p++) {
            int a0 = __dp4a(YL[p + 1], wsh[32], wsh[44]);
            a0     = __dp4a(YH[p + 1], wsh[33], a0);
            a0     = __dp4a(YL[p + 2], wsh[34], a0);
            a0     = __dp4a(YH[p + 2], wsh[35], a0);
            a0     = __dp4a(YL[p + 3], wsh[36], a0);
            a0     = __dp4a(YH[p + 3], wsh[37], a0);
            int a1 = __dp4a(YL[p + 1], wsh[38], wsh[45]);
            a1     = __dp4a(YH[p + 1], wsh[39], a1);
            a1     = __dp4a(YL[p + 2], wsh[40], a1);
            a1     = __dp4a(YH[p + 2], wsh[41], a1);
            a1     = __dp4a(YL[p + 3], wsh[42], a1);
            a1     = __dp4a(YH[p + 3], wsh[43], a1);
            f0[p] = (float)min(max(a0 >> 7, -128), 127) * 0.0078125f;
            f1[p] = (float)min(max(a1 >> 7, -128), 127) * 0.0078125f;
        }
        *(float4*)(ob + ts + j)             = make_float4(f0[0], f0[1], f0[2], f0[3]);
        *(float4*)(ob + (size_t)L + ts + j) = make_float4(f1[0], f1[1], f1[2], f1[3]);
    }
}

__global__ __launch_bounds__(NT, 8) void fused_qconv_occ8(
    const float* __restrict__ x,
    const float* __restrict__ w1, const float* __restrict__ b1,
    const float* __restrict__ gamma, const float* __restrict__ beta,
    const float* __restrict__ bn_mean, const float* __restrict__ bn_var,
    const float* __restrict__ w2, const float* __restrict__ b2,
    float* __restrict__ out, int L)
{
    __shared__ int wsh[48];
    extern __shared__ int smem[];
    int* xs  = smem;                 // [TL+8]  packed x, xs[i] = pos ts-4+i
    int* ysL = smem + (TL + 8);      // [TL+4]  y ch0..3, ysL[i] = pos ts-2+i
    int* ysH = ysL + (TL + 4);       // [TL+4]  y ch4..7

    const int tid = threadIdx.x;
    const int bb  = blockIdx.y;
    const int ts  = blockIdx.x * TL;
    const float* xb = x + (size_t)bb * 4 * L;
    const bool edge = (blockIdx.x == 0) | (blockIdx.x == gridDim.x - 1);

    // ---- halos + tiny weight set (disjoint tid ranges) ----
    if (tid < 4) {                                // left halo: pos ts-4+tid
        int p = ts - 4 + tid, w = 0;
        if (p >= 0)
            w = qpack(xb[p], xb[(size_t)L + p],
                      xb[(size_t)2*L + p], xb[(size_t)3*L + p]);
        xs[tid] = w;
    } else if (tid < 8) {                         // right halo
        int p = ts + TL + (tid - 4), w = 0;
        if (p < L)
            w = qpack(xb[p], xb[(size_t)L + p],
                      xb[(size_t)2*L + p], xb[(size_t)3*L + p]);
        xs[TL + 4 + (tid - 4)] = w;
    } else if (tid >= 32 && tid < 56) {           // w1 packed
        int t = tid - 32, oc = t / 3, k = t % 3;
        float sf = (float)((double)gamma[oc] / sqrt((double)bn_var[oc] + 1e-5));
        const float* wb = w1 + oc * 12 + k;
        wsh[t] = qpack(wb[0] * sf, wb[3] * sf, wb[6] * sf, wb[9] * sf);
    } else if (tid >= 56 && tid < 64) {           // folded bias 1
        int oc = tid - 56;
        float sf = (float)((double)gamma[oc] / sqrt((double)bn_var[oc] + 1e-5));
        int bi = min(max(cvtrd((b1[oc] - bn_mean[oc]) * sf + beta[oc]), -128), 127);
        wsh[24 + oc] = bi * 128 + 64;
    } else if (tid >= 64 && tid < 76) {           // w2 packed
        int t = tid - 64, oc = t / 6, r = t % 6, k = r >> 1, h = r & 1;
        const float* wb = w2 + oc * 24 + h * 12 + k;
        wsh[32 + t] = qpack(wb[0], wb[3], wb[6], wb[9]);
    } else if (tid >= 76 && tid < 78) {           // bias 2
        int oc = tid - 76;
        wsh[44 + oc] = min(max(cvtrd(b2[oc]), -128), 127) * 128 + 64;
    }

    // ---- stage 1: float4 load + quantize + pack 4 ch/word ----
    for (int g = tid; g < TL / 4; g += NT) {
        int p = ts + 4 * g;
        float4 a = *(const float4*)(xb + p);
        float4 b = *(const float4*)(xb + (size_t)L + p);
        float4 c = *(const float4*)(xb + (size_t)2 * L + p);
        float4 d = *(const float4*)(xb + (size_t)3 * L + p);
        int4 w;
        w.x = qpack(a.x, b.x, c.x, d.x);
        w.y = qpack(a.y, b.y, c.y, d.y);
        w.z = qpack(a.z, b.z, c.z, d.z);
        w.w = qpack(a.w, b.w, c.w, d.w);
        *(int4*)(xs + 4 + 4 * g) = w;
    }
    __syncthreads();

    float* ob = out + (size_t)bb * 2 * L;
    if (edge) stages23<true >(xs, ysL, ysH, wsh, tid, ts, L, ob);
    else      stages23<false>(xs, ysL, ysH, wsh, tid, ts, L, ob);
}

extern "C" void kernel_launch(void* const* d_in, const int* in_sizes, int n_in,
                              void* d_out, int out_size)
{
    const float* x       = (const float*)d_in[0];
    const float* w1      = (const float*)d_in[1];
    const float* b1      = (const float*)d_in[2];
    const float* gamma   = (const float*)d_in[3];
    const float* beta    = (const float*)d_in[4];
    const float* bn_mean = (const float*)d_in[5];
    const float* bn_var  = (const float*)d_in[6];
    const float* w2      = (const float*)d_in[7];
    const float* b2      = (const float*)d_in[8];
    float* out = (float*)d_out;

    const int B = 16;
    const int L = in_sizes[0] / (B * 4);

    const int smem_bytes = ((TL + 8) + 2 * (TL + 4)) * (int)sizeof(int); // 24.6KB

    dim3 grid((L + TL - 1) / TL, B);
    fused_qconv_occ8<<<grid, NT, smem_bytes>>>(
        x, w1, b1, gamma, beta, bn_mean, bn_var, w2, b2, out, L);
}

// round 11
// speedup vs baseline: 1.3973x; 1.3973x over previous
#include <cuda_runtime.h>
#include <cstdint>

// Integer-exact fused QAT conv stack (bit-exact vs fp32 reference).
// 3-stage smem design (R9 body), smaller sync domains: NT=128, TL=1024,
// 12 blocks/SM (__launch_bounds__(128,12), ~42 regs). f32x2 quant FMAs.

#define TL 1024      // tile positions per block
#define NT 128       // threads per block

__device__ __forceinline__ int cvtrd(float v) {
    return __float2int_rd(fmaf(v, 128.0f, 0.5f));   // floor(v*128 + 0.5)
}
__device__ __forceinline__ int packsat2(int a, int b, int c) {
    int d;
    asm("cvt.pack.sat.s8.s32.b32 %0, %1, %2, %3;"
        : "=r"(d) : "r"(a), "r"(b), "r"(c));
    return d;
}
// bytes perm of [v0..v3]; same helper for weights and data -> dp4a invariant
__device__ __forceinline__ int pack4sat(int v0, int v1, int v2, int v3) {
    return packsat2(v1, v0, packsat2(v3, v2, 0));
}
__device__ __forceinline__ int qpack(float a, float b, float c, float d) {
    return pack4sat(cvtrd(a), cvtrd(b), cvtrd(c), cvtrd(d));
}

// Packed pairwise v*128+0.5 via Blackwell fma.rn.f32x2, then floor-cvt each.
// Bit-exact: f32x2 lanes are IEEE fma on each half, identical to scalar fmaf.
__device__ __forceinline__ int qpackv(float a, float b, float c, float d) {
    const uint64_t K128 = 0x4300000043000000ULL;  // {128.0f,128.0f}
    const uint64_t K05  = 0x3F0000003F000000ULL;  // {0.5f,0.5f}
    uint64_t p0, p1, r0, r1;
    asm("mov.b64 %0, {%1, %2};" : "=l"(p0) : "f"(a), "f"(b));
    asm("mov.b64 %0, {%1, %2};" : "=l"(p1) : "f"(c), "f"(d));
    asm("fma.rn.f32x2 %0, %1, %2, %3;" : "=l"(r0) : "l"(p0), "l"(K128), "l"(K05));
    asm("fma.rn.f32x2 %0, %1, %2, %3;" : "=l"(r1) : "l"(p1), "l"(K128), "l"(K05));
    float f0, f1, f2, f3;
    asm("mov.b64 {%0, %1}, %2;" : "=f"(f0), "=f"(f1) : "l"(r0));
    asm("mov.b64 {%0, %1}, %2;" : "=f"(f2), "=f"(f3) : "l"(r1));
    int i0, i1, i2, i3;
    asm("cvt.rmi.s32.f32 %0, %1;" : "=r"(i0) : "f"(f0));
    asm("cvt.rmi.s32.f32 %0, %1;" : "=r"(i1) : "f"(f1));
    asm("cvt.rmi.s32.f32 %0, %1;" : "=r"(i2) : "f"(f2));
    asm("cvt.rmi.s32.f32 %0, %1;" : "=r"(i3) : "f"(f3));
    return pack4sat(i0, i1, i2, i3);
}

// Stages 2+3, templated on EDGE so interior blocks get a branch-free body.
// wsh: [0..23] w1p (oc*3+k), [24..31] bo1, [32..43] w2p, [44..45] bo2
template <bool EDGE>
__device__ __forceinline__ void stages23(
    const int* __restrict__ xs, int* __restrict__ ysL, int* __restrict__ ysH,
    const int* __restrict__ wsh, int tid, int ts, int L, float* __restrict__ ob)
{
    // ---- stage 2: y = satpack((conv1 + 128*b + 64) >> 7), 4 pos/thread ----
    for (int g = tid; g < (TL + 4) / 4; g += NT) {
        int m = 4 * g;
        int4 va = *(const int4*)(xs + m);
        int4 vb = *(const int4*)(xs + m + 4);
        int xv[8] = {va.x, va.y, va.z, va.w, vb.x, vb.y, vb.z, vb.w};
        int lo[4], hi[4];
#pragma unroll
        for (int p = 0; p < 4; p++) {
            int x0 = xv[p + 1], x1 = xv[p + 2], x2 = xv[p + 3];
            int yv[8];
#pragma unroll
            for (int oc = 0; oc < 8; oc++) {
                int acc = __dp4a(x0, wsh[oc * 3 + 0], wsh[24 + oc]);
                acc     = __dp4a(x1, wsh[oc * 3 + 1], acc);
                acc     = __dp4a(x2, wsh[oc * 3 + 2], acc);
                yv[oc]  = acc >> 7;
            }
            lo[p] = pack4sat(yv[0], yv[1], yv[2], yv[3]);
            hi[p] = pack4sat(yv[4], yv[5], yv[6], yv[7]);
            if (EDGE) {
                int q = ts - 2 + m + p;
                bool valid = (q >= 0) && (q < L);
                lo[p] = valid ? lo[p] : 0;
                hi[p] = valid ? hi[p] : 0;
            }
        }
        *(int4*)(ysL + m) = make_int4(lo[0], lo[1], lo[2], lo[3]);
        *(int4*)(ysH + m) = make_int4(hi[0], hi[1], hi[2], hi[3]);
    }
    __syncthreads();

    // ---- stage 3: z = dequant(clamp((conv2 + 128*b + 64) >> 7)), 4 pos ----
    for (int g = tid; g < TL / 4; g += NT) {
        int j = 4 * g;
        int4 la = *(const int4*)(ysL + j);
        int4 lb = *(const int4*)(ysL + j + 4);
        int4 ha = *(const int4*)(ysH + j);
        int4 hb = *(const int4*)(ysH + j + 4);
        int YL[8] = {la.x, la.y, la.z, la.w, lb.x, lb.y, lb.z, lb.w};
        int YH[8] = {ha.x, ha.y, ha.z, ha.w, hb.x, hb.y, hb.z, hb.w};
        float f0[4], f1[4];
#pragma unroll
        for (int p = 0; p < 4; p++) {
            int a0 = __dp4a(YL[p + 1], wsh[32], wsh[44]);
            a0     = __dp4a(YH[p + 1], wsh[33], a0);
            a0     = __dp4a(YL[p + 2], wsh[34], a0);
            a0     = __dp4a(YH[p + 2], wsh[35], a0);
            a0     = __dp4a(YL[p + 3], wsh[36], a0);
            a0     = __dp4a(YH[p + 3], wsh[37], a0);
            int a1 = __dp4a(YL[p + 1], wsh[38], wsh[45]);
            a1     = __dp4a(YH[p + 1], wsh[39], a1);
            a1     = __dp4a(YL[p + 2], wsh[40], a1);
            a1     = __dp4a(YH[p + 2], wsh[41], a1);
            a1     = __dp4a(YL[p + 3], wsh[42], a1);
            a1     = __dp4a(YH[p + 3], wsh[43], a1);
            f0[p] = (float)min(max(a0 >> 7, -128), 127) * 0.0078125f;
            f1[p] = (float)min(max(a1 >> 7, -128), 127) * 0.0078125f;
        }
        *(float4*)(ob + ts + j)             = make_float4(f0[0], f0[1], f0[2], f0[3]);
        *(float4*)(ob + (size_t)L + ts + j) = make_float4(f1[0], f1[1], f1[2], f1[3]);
    }
}

__global__ __launch_bounds__(NT, 12) void fused_qconv_b128(
    const float* __restrict__ x,
    const float* __restrict__ w1, const float* __restrict__ b1,
    const float* __restrict__ gamma, const float* __restrict__ beta,
    const float* __restrict__ bn_mean, const float* __restrict__ bn_var,
    const float* __restrict__ w2, const float* __restrict__ b2,
    float* __restrict__ out, int L)
{
    __shared__ int wsh[48];
    extern __shared__ int smem[];
    int* xs  = smem;                 // [TL+8]  packed x, xs[i] = pos ts-4+i
    int* ysL = smem + (TL + 8);      // [TL+4]  y ch0..3, ysL[i] = pos ts-2+i
    int* ysH = ysL + (TL + 4);       // [TL+4]  y ch4..7

    const int tid = threadIdx.x;
    const int bb  = blockIdx.y;
    const int ts  = blockIdx.x * TL;
    const float* xb = x + (size_t)bb * 4 * L;
    const bool edge = (blockIdx.x == 0) | (blockIdx.x == gridDim.x - 1);

    // ---- halos + tiny weight set (disjoint tid ranges) ----
    if (tid < 4) {                                // left halo: pos ts-4+tid
        int p = ts - 4 + tid, w = 0;
        if (p >= 0)
            w = qpack(xb[p], xb[(size_t)L + p],
                      xb[(size_t)2*L + p], xb[(size_t)3*L + p]);
        xs[tid] = w;
    } else if (tid < 8) {                         // right halo
        int p = ts + TL + (tid - 4), w = 0;
        if (p < L)
            w = qpack(xb[p], xb[(size_t)L + p],
                      xb[(size_t)2*L + p], xb[(size_t)3*L + p]);
        xs[TL + 4 + (tid - 4)] = w;
    } else if (tid >= 32 && tid < 56) {           // w1 packed
        int t = tid - 32, oc = t / 3, k = t % 3;
        float sf = (float)((double)gamma[oc] / sqrt((double)bn_var[oc] + 1e-5));
        const float* wb = w1 + oc * 12 + k;
        wsh[t] = qpack(wb[0] * sf, wb[3] * sf, wb[6] * sf, wb[9] * sf);
    } else if (tid >= 56 && tid < 64) {           // folded bias 1
        int oc = tid - 56;
        float sf = (float)((double)gamma[oc] / sqrt((double)bn_var[oc] + 1e-5));
        int bi = min(max(cvtrd((b1[oc] - bn_mean[oc]) * sf + beta[oc]), -128), 127);
        wsh[24 + oc] = bi * 128 + 64;
    } else if (tid >= 64 && tid < 76) {           // w2 packed
        int t = tid - 64, oc = t / 6, r = t % 6, k = r >> 1, h = r & 1;
        const float* wb = w2 + oc * 24 + h * 12 + k;
        wsh[32 + t] = qpack(wb[0], wb[3], wb[6], wb[9]);
    } else if (tid >= 76 && tid < 78) {           // bias 2
        int oc = tid - 76;
        wsh[44 + oc] = min(max(cvtrd(b2[oc]), -128), 127) * 128 + 64;
    }

    // ---- stage 1: float4 load + f32x2 quantize + pack 4 ch/word ----
    for (int g = tid; g < TL / 4; g += NT) {
        int p = ts + 4 * g;
        float4 a = *(const float4*)(xb + p);
        float4 b = *(const float4*)(xb + (size_t)L + p);
        float4 c = *(const float4*)(xb + (size_t)2 * L + p);
        float4 d = *(const float4*)(xb + (size_t)3 * L + p);
        int4 w;
        w.x = qpackv(a.x, b.x, c.x, d.x);
        w.y = qpackv(a.y, b.y, c.y, d.y);
        w.z = qpackv(a.z, b.z, c.z, d.z);
        w.w = qpackv(a.w, b.w, c.w, d.w);
        *(int4*)(xs + 4 + 4 * g) = w;
    }
    __syncthreads();

    float* ob = out + (size_t)bb * 2 * L;
    if (edge) stages23<true >(xs, ysL, ysH, wsh, tid, ts, L, ob);
    else      stages23<false>(xs, ysL, ysH, wsh, tid, ts, L, ob);
}

extern "C" void kernel_launch(void* const* d_in, const int* in_sizes, int n_in,
                              void* d_out, int out_size)
{
    const float* x       = (const float*)d_in[0];
    const float* w1      = (const float*)d_in[1];
    const float* b1      = (const float*)d_in[2];
    const float* gamma   = (const float*)d_in[3];
    const float* beta    = (const float*)d_in[4];
    const float* bn_mean = (const float*)d_in[5];
    const float* bn_var  = (const float*)d_in[6];
    const float* w2      = (const float*)d_in[7];
    const float* b2      = (const float*)d_in[8];
    float* out = (float*)d_out;

    const int B = 16;
    const int L = in_sizes[0] / (B * 4);

    const int smem_bytes = ((TL + 8) + 2 * (TL + 4)) * (int)sizeof(int); // 12.3KB

    dim3 grid((L + TL - 1) / TL, B);
    fused_qconv_b128<<<grid, NT, smem_bytes>>>(
        x, w1, b1, gamma, beta, bn_mean, bn_var, w2, b2, out, L);
}

// round 12
// speedup vs baseline: 1.5149x; 1.0842x over previous
#include <cuda_runtime.h>

// Integer-exact fused QAT conv stack (bit-exact vs fp32 reference).
// R4 all-register body (8 pos/thread, no barriers, no smem data flow),
// loads restructured into 4 groups to cut live registers; 5 blocks/SM.

#define NT 256   // threads per block
#define PP 8     // output positions per thread

__device__ __forceinline__ int cvtrd(float v) {
    return __float2int_rd(fmaf(v, 128.0f, 0.5f));   // floor(v*128 + 0.5)
}
__device__ __forceinline__ int packsat2(int a, int b, int c) {
    int d;
    asm("cvt.pack.sat.s8.s32.b32 %0, %1, %2, %3;"
        : "=r"(d) : "r"(a), "r"(b), "r"(c));
    return d;
}
// bytes perm of [v0..v3]; same helper for weights and data -> dp4a invariant
__device__ __forceinline__ int pack4sat(int v0, int v1, int v2, int v3) {
    return packsat2(v1, v0, packsat2(v3, v2, 0));
}
__device__ __forceinline__ int qpack(float a, float b, float c, float d) {
    return pack4sat(cvtrd(a), cvtrd(b), cvtrd(c), cvtrd(d));
}

// wall layout: [0..23] w1 packed (oc*3+k), [24..31] 128*b1+64,
//              [32..43] w2 packed (oc*6+k*2+h), [44..45] 128*b2+64
template <bool GUARD>
__device__ __forceinline__ void tail_compute(
    const int* xw, const int* wall, int base, int L, float* ob)
{
    int yl[PP + 2], yh[PP + 2];
#pragma unroll
    for (int i = 0; i < PP + 2; i++) {
        int x0 = xw[i], x1 = xw[i + 1], x2 = xw[i + 2];
        int yv[8];
#pragma unroll
        for (int oc = 0; oc < 8; oc++) {
            int acc = __dp4a(x0, wall[oc * 3 + 0], wall[24 + oc]);
            acc     = __dp4a(x1, wall[oc * 3 + 1], acc);
            acc     = __dp4a(x2, wall[oc * 3 + 2], acc);
            yv[oc]  = acc >> 7;
        }
        int lo = pack4sat(yv[0], yv[1], yv[2], yv[3]);
        int hi = pack4sat(yv[4], yv[5], yv[6], yv[7]);
        if (GUARD) {
            int q = base - 1 + i;
            bool valid = (q >= 0) && (q < L);
            lo = valid ? lo : 0;
            hi = valid ? hi : 0;
        }
        yl[i] = lo; yh[i] = hi;
    }

    float f0[PP], f1[PP];
#pragma unroll
    for (int p = 0; p < PP; p++) {
        int a0 = __dp4a(yl[p],     wall[32], wall[44]);
        a0     = __dp4a(yh[p],     wall[33], a0);
        a0     = __dp4a(yl[p + 1], wall[34], a0);
        a0     = __dp4a(yh[p + 1], wall[35], a0);
        a0     = __dp4a(yl[p + 2], wall[36], a0);
        a0     = __dp4a(yh[p + 2], wall[37], a0);
        int a1 = __dp4a(yl[p],     wall[38], wall[45]);
        a1     = __dp4a(yh[p],     wall[39], a1);
        a1     = __dp4a(yl[p + 1], wall[40], a1);
        a1     = __dp4a(yh[p + 1], wall[41], a1);
        a1     = __dp4a(yl[p + 2], wall[42], a1);
        a1     = __dp4a(yh[p + 2], wall[43], a1);
        f0[p] = (float)min(max(a0 >> 7, -128), 127) * 0.0078125f;
        f1[p] = (float)min(max(a1 >> 7, -128), 127) * 0.0078125f;
    }
    *(float4*)(ob + base)         = make_float4(f0[0], f0[1], f0[2], f0[3]);
    *(float4*)(ob + base + 4)     = make_float4(f0[4], f0[5], f0[6], f0[7]);
    *(float4*)(ob + (size_t)L + base)     = make_float4(f1[0], f1[1], f1[2], f1[3]);
    *(float4*)(ob + (size_t)L + base + 4) = make_float4(f1[4], f1[5], f1[6], f1[7]);
}

__global__ __launch_bounds__(NT, 5) void fused_qconv_reg5(
    const float* __restrict__ x,
    const float* __restrict__ w1, const float* __restrict__ b1,
    const float* __restrict__ gamma, const float* __restrict__ beta,
    const float* __restrict__ bn_mean, const float* __restrict__ bn_var,
    const float* __restrict__ w2, const float* __restrict__ b2,
    float* __restrict__ out, int L)
{
    __shared__ int wall[48];
    const int tid = threadIdx.x;

    // ---- weight prep (tiny, once per block) ----
    if (tid < 24) {
        int oc = tid / 3, k = tid % 3;
        float sf = (float)((double)gamma[oc] / sqrt((double)bn_var[oc] + 1e-5));
        const float* wb = w1 + oc * 12 + k;
        wall[tid] = qpack(wb[0] * sf, wb[3] * sf, wb[6] * sf, wb[9] * sf);
    } else if (tid < 32) {
        int oc = tid - 24;
        float sf = (float)((double)gamma[oc] / sqrt((double)bn_var[oc] + 1e-5));
        int bi = min(max(cvtrd((b1[oc] - bn_mean[oc]) * sf + beta[oc]), -128), 127);
        wall[tid] = bi * 128 + 64;
    } else if (tid < 44) {
        int t = tid - 32, oc = t / 6, r = t % 6, k = r >> 1, h = r & 1;
        const float* wb = w2 + oc * 24 + h * 12 + k;
        wall[tid] = qpack(wb[0], wb[3], wb[6], wb[9]);
    } else if (tid < 46) {
        wall[tid] = min(max(cvtrd(b2[tid - 44]), -128), 127) * 128 + 64;
    }
    __syncthreads();

    const int bb   = blockIdx.y;
    const int base = (blockIdx.x * NT + tid) * PP;   // first z position
    const float* xb = x + (size_t)bb * 4 * L;
    float* ob = out + (size_t)bb * 2 * L;

    int xw[12];   // packed fq(x), xw[j] = position base-2+j

    if (base >= 4 && base + 12 <= L) {
        // ---- fast path: 4 groups of 4 aligned float4 loads ----
        // (grouped to keep <=16 floats live -> lower register pressure)
        const float* p0 = xb + (base - 4);
#pragma unroll
        for (int g = 0; g < 4; g++) {
            const float* q = p0 + 4 * g;
            float4 a = *(const float4*)(q);
            float4 b = *(const float4*)(q + (size_t)L);
            float4 c = *(const float4*)(q + (size_t)2 * L);
            float4 d = *(const float4*)(q + (size_t)3 * L);
            if (g == 0) {
                // only the last two positions of the first group are needed
                xw[0] = qpack(a.z, b.z, c.z, d.z);
                xw[1] = qpack(a.w, b.w, c.w, d.w);
            } else {
                xw[4 * g - 2] = qpack(a.x, b.x, c.x, d.x);
                xw[4 * g - 1] = qpack(a.y, b.y, c.y, d.y);
                xw[4 * g + 0] = qpack(a.z, b.z, c.z, d.z);
                xw[4 * g + 1] = qpack(a.w, b.w, c.w, d.w);
            }
        }
        tail_compute<false>(xw, wall, base, L, ob);
    } else {
        // ---- slow path: batch-row edges only (2 threads per row) ----
#pragma unroll
        for (int j = 0; j < 12; j++) {
            int p = base - 2 + j, w = 0;
            if (p >= 0 && p < L)
                w = qpack(xb[p], xb[(size_t)L + p],
                          xb[(size_t)2 * L + p], xb[(size_t)3 * L + p]);
            xw[j] = w;
        }
        tail_compute<true>(xw, wall, base, L, ob);
    }
}

extern "C" void kernel_launch(void* const* d_in, const int* in_sizes, int n_in,
                              void* d_out, int out_size)
{
    const float* x       = (const float*)d_in[0];
    const float* w1      = (const float*)d_in[1];
    const float* b1      = (const float*)d_in[2];
    const float* gamma   = (const float*)d_in[3];
    const float* beta    = (const float*)d_in[4];
    const float* bn_mean = (const float*)d_in[5];
    const float* bn_var  = (const float*)d_in[6];
    const float* w2      = (const float*)d_in[7];
    const float* b2      = (const float*)d_in[8];
    float* out = (float*)d_out;

    const int B = 16;
    const int L = in_sizes[0] / (B * 4);

    dim3 grid(L / (NT * PP), B);
    fused_qconv_reg5<<<grid, NT>>>(
        x, w1, b1, gamma, beta, bn_mean, bn_var, w2, b2, out, L);
}